// round 8
// baseline (speedup 1.0000x reference)
#include <cuda_runtime.h>
#include <stdint.h>

// ---------------------------------------------------------------------------
// Token-choice router (training mode, Gumbel-softmax), matching the JAX ref:
//   logits = x @ W^T + b ; stabilize ; + threefry-normal*0.05 ; clip
//   soft_probs = softmax(logits) ; entropy/expected_steps means
//   routing_weights = softmax(logits + gumbel(key 2)*0.5)
// Output layout: [rw (T*E)] [entropy (1)] [expected_steps (1)] [soft (T*E)]
// RNG: JAX threefry2x32, *partitionable* scheme (default since JAX 0.4.30):
//   bits(i) = r0 ^ r1 where (r0,r1) = threefry(key, (hi64(i), lo64(i))) = (0, i)
// ---------------------------------------------------------------------------

__device__ float g_ent_acc;
__device__ float g_exp_acc;

__device__ __forceinline__ unsigned long long fma2(unsigned long long a,
                                                   unsigned long long b,
                                                   unsigned long long c) {
    unsigned long long d;
    asm("fma.rn.f32x2 %0, %1, %2, %3;" : "=l"(d) : "l"(a), "l"(b), "l"(c));
    return d;
}

__device__ __forceinline__ void unpack2(unsigned long long v, float& lo, float& hi) {
    asm("mov.b64 {%0, %1}, %2;" : "=f"(lo), "=f"(hi) : "l"(v));
}

__device__ __forceinline__ uint32_t rotl32(uint32_t v, int r) {
    return (v << r) | (v >> (32 - r));
}

// JAX threefry2x32 (20 rounds), key = (k0, k1), counter = (c0, c1)
__device__ __forceinline__ void threefry2x32(uint32_t k0, uint32_t k1,
                                             uint32_t c0, uint32_t c1,
                                             uint32_t& r0, uint32_t& r1) {
    uint32_t ks2 = 0x1BD11BDAu ^ k0 ^ k1;
    uint32_t x0 = c0 + k0;
    uint32_t x1 = c1 + k1;
#define TF_R(r) { x0 += x1; x1 = rotl32(x1, r); x1 ^= x0; }
    TF_R(13) TF_R(15) TF_R(26) TF_R(6)
    x0 += k1;  x1 += ks2 + 1u;
    TF_R(17) TF_R(29) TF_R(16) TF_R(24)
    x0 += ks2; x1 += k0 + 2u;
    TF_R(13) TF_R(15) TF_R(26) TF_R(6)
    x0 += k0;  x1 += k1 + 3u;
    TF_R(17) TF_R(29) TF_R(16) TF_R(24)
    x0 += k1;  x1 += ks2 + 4u;
    TF_R(13) TF_R(15) TF_R(26) TF_R(6)
    x0 += ks2; x1 += k0 + 5u;
#undef TF_R
    r0 = x0; r1 = x1;
}

// JAX partitionable random_bits (32-bit): counter = 64-bit flat index as
// (hi, lo) 32-bit words; for idx < 2^32 that is (0, idx). Output = r0 ^ r1.
__device__ __forceinline__ uint32_t jax_random_bits(uint32_t key_lo, uint32_t idx) {
    uint32_t r0, r1;
    threefry2x32(0u, key_lo, 0u, idx, r0, r1);
    return r0 ^ r1;
}

__device__ __forceinline__ float max8(float v) {
    v = fmaxf(v, __shfl_xor_sync(0xFFFFFFFFu, v, 1));
    v = fmaxf(v, __shfl_xor_sync(0xFFFFFFFFu, v, 2));
    v = fmaxf(v, __shfl_xor_sync(0xFFFFFFFFu, v, 4));
    return v;
}

__device__ __forceinline__ float sum8(float v) {
    v += __shfl_xor_sync(0xFFFFFFFFu, v, 1);
    v += __shfl_xor_sync(0xFFFFFFFFu, v, 2);
    v += __shfl_xor_sync(0xFFFFFFFFu, v, 4);
    return v;
}

// One warp handles 4 consecutive tokens; E = 8 experts fixed.
__global__ __launch_bounds__(256, 2) void router_kernel(
    const float* __restrict__ x, const float* __restrict__ W,
    const float* __restrict__ bias, float* __restrict__ out, int T, int D) {
    extern __shared__ unsigned char smem_raw[];
    ulonglong2* ws2 = reinterpret_cast<ulonglong2*>(smem_raw);
    const int D4 = D >> 2;  // ulonglong2 (4 floats) per row

    {   // Stage W (E x D fp32, 64KB) into shared memory
        const ulonglong2* Wg = reinterpret_cast<const ulonglong2*>(W);
        const int nW = D4 * 8;
        for (int j = threadIdx.x; j < nW; j += 256) ws2[j] = Wg[j];
    }
    __syncthreads();

    const int warp = threadIdx.x >> 5;
    const int lane = threadIdx.x & 31;
    const int t0 = (blockIdx.x * 8 + warp) * 4;
    if (t0 >= T) return;

    // Packed f32x2 accumulators: [token][expert]
    unsigned long long acc[4][8];
#pragma unroll
    for (int t = 0; t < 4; t++)
#pragma unroll
        for (int e = 0; e < 8; e++) acc[t][e] = 0ull;

    const ulonglong2* xp =
        reinterpret_cast<const ulonglong2*>(x) + (size_t)t0 * D4 + lane;
    const int niter = D >> 7;  // 128 floats (32 lanes * 4) per iter
#pragma unroll 4
    for (int i = 0; i < niter; i++) {
        ulonglong2 xv[4];
#pragma unroll
        for (int t = 0; t < 4; t++) xv[t] = xp[(size_t)t * D4 + i * 32];
        const ulonglong2* wr = ws2 + i * 32 + lane;
#pragma unroll
        for (int e = 0; e < 8; e++) {
            ulonglong2 wv = wr[e * D4];
#pragma unroll
            for (int t = 0; t < 4; t++) {
                acc[t][e] = fma2(xv[t].x, wv.x, acc[t][e]);
                acc[t][e] = fma2(xv[t].y, wv.y, acc[t][e]);
            }
        }
    }

    // Cross-lane reduce all 32 (token,expert) partial sums; lane (t*8+e) keeps its own.
    float mine = 0.0f;
#pragma unroll
    for (int t = 0; t < 4; t++) {
#pragma unroll
        for (int e = 0; e < 8; e++) {
            float lo, hi;
            unpack2(acc[t][e], lo, hi);
            float v = lo + hi;
#pragma unroll
            for (int d = 16; d >= 1; d >>= 1)
                v += __shfl_xor_sync(0xFFFFFFFFu, v, d);
            if (lane == t * 8 + e) mine = v;
        }
    }

    const int e = lane & 7;
    const int tok = t0 + (lane >> 3);

    float logit = mine + __ldg(bias + e);
    float l = logit - max8(logit);  // numerical stabilization (ref)

    const uint32_t nelem = (uint32_t)T * 8u;
    const uint32_t idx = (uint32_t)tok * 8u + (uint32_t)e;

    // training noise: jax.random.normal(key(1)) * 0.05, then clip
    {
        uint32_t bits = jax_random_bits(1u, idx);
        float f01 = __uint_as_float((bits >> 9) | 0x3f800000u) - 1.0f;  // [0,1)
        const float LOV = -0.99999994f;  // nextafter(-1, 0)
        float u = fmaxf(LOV, f01 * 2.0f + LOV);  // (hi-lo) rounds to 2.0f
        float noise = 1.4142135623730951f * erfinvf(u) * 0.05f;
        l = fminf(fmaxf(l + noise, -50.0f), 50.0f);
    }
    // inv_t = 1/(1+1e-8) == 1.0f exactly in fp32 -> omit

    // soft_probs = softmax(l)
    float p = expf(l - max8(l));
    float soft = p / sum8(p);

    float ent = sum8(-soft * logf(soft + 1e-8f));   // per-token entropy
    float est = sum8(soft * (float)e);              // per-token expected step

    // routing_weights = softmax(l + gumbel(key(2)) * 0.5)
    float rw;
    {
        uint32_t bits = jax_random_bits(2u, idx);
        float u2 = __uint_as_float((bits >> 9) | 0x3f800000u) - 1.0f;
        float g = -logf(-logf(u2 + 1e-8f) + 1e-8f) * 0.5f;
        float r = l + g;
        float q = expf(r - max8(r));
        rw = q / sum8(q);
    }

    out[idx] = rw;
    out[(size_t)nelem + 2 + idx] = soft;

    // Per-warp scalar accumulation (4 tokens): groups hold identical ent/est
    float entw = ent + __shfl_xor_sync(0xFFFFFFFFu, ent, 8);
    entw += __shfl_xor_sync(0xFFFFFFFFu, entw, 16);
    float estw = est + __shfl_xor_sync(0xFFFFFFFFu, est, 8);
    estw += __shfl_xor_sync(0xFFFFFFFFu, estw, 16);
    if (lane == 0) {
        atomicAdd(&g_ent_acc, entw);
        atomicAdd(&g_exp_acc, estw);
    }
}

__global__ void zero_acc_kernel() {
    g_ent_acc = 0.0f;
    g_exp_acc = 0.0f;
}

__global__ void finalize_kernel(float* __restrict__ out, uint32_t nelem, float invT) {
    float ent = g_ent_acc * invT;
    out[nelem] = fminf(fmaxf(ent, 0.0f), 20.0f);
    out[nelem + 1] = g_exp_acc * invT;
}

extern "C" void kernel_launch(void* const* d_in, const int* in_sizes, int n_in,
                              void* d_out, int out_size) {
    const float* x = (const float*)d_in[0];
    const float* W = (const float*)d_in[1];
    const float* b = (const float*)d_in[2];
    float* out = (float*)d_out;

    const int E = in_sizes[2];       // 8
    const int D = in_sizes[1] / E;   // 2048
    const int T = in_sizes[0] / D;   // 16384

    size_t smem = (size_t)E * D * sizeof(float);  // 64 KB
    cudaFuncSetAttribute(router_kernel,
                         cudaFuncAttributeMaxDynamicSharedMemorySize, (int)smem);

    zero_acc_kernel<<<1, 1>>>();
    int blocks = T / 32;  // 8 warps/CTA * 4 tokens/warp
    router_kernel<<<blocks, 256, smem>>>(x, W, b, out, T, D);
    finalize_kernel<<<1, 1>>>(out, (uint32_t)T * (uint32_t)E, 1.0f / (float)T);
}